// round 16
// baseline (speedup 1.0000x reference)
#include <cuda_runtime.h>
#include <cuda_fp16.h>

#define HH 128
#define WW 128
#define CC 16
#define NPIX (HH*WW)
#define NRES 5
#define NLINES (NRES*NPIX)
#define NPTS 32
#define SCALE 5.0f
#define LOI_ELEMS (NLINES*CC*NPTS)
#define TOPK_BLOCKS (NPIX/8)        // 2048 blocks, 1 warp per candidate
#define LOI_BLOCKS  (NLINES/8)      // 10240 blocks, 1 warp per line

// scratch (no allocations allowed)
// g_tfeat layout: 2x2-pixel quads, 64 halfs (128B) per quad, separable:
//   half_index = Y(y) + X(x) + c,  Y(y)=(y&~1)<<11 | (y&1)<<5,  X(x)=(x&~1)<<5 | (x&1)<<4
__device__ __half g_tfeat[NPIX*CC];      // 0.5 MB
__device__ float4 g_lparam[NPIX];        // 256 KB, per-pixel (ax_st,ay_st,ax_ed,ay_ed)
__device__ float  g_cand_v[NPIX];
__device__ int    g_cand_i[NPIX];
__device__ int    g_zero_i[NPIX];
__device__ int    g_cnt[2];              // zero-init; self-resetting (see k_main)
__device__ int    g_done;                // zero-init; self-resetting

// features->fp16 quad-tiled, per-pixel hafm direction params, NMS + compaction
__global__ void __launch_bounds__(256) k_prep(
    const float* __restrict__ feat, const float* __restrict__ jloc,
    const float* __restrict__ md)
{
    __shared__ float s[CC*257];
    int tid = threadIdx.x;
    int idx = blockIdx.x * 256 + tid;
    int x = idx & (WW-1), y = idx >> 7;

    #pragma unroll
    for (int c = 0; c < CC; ++c)
        s[c*257 + tid] = feat[c*NPIX + idx];
    __syncthreads();
    {
        unsigned r[8];
        #pragma unroll
        for (int j = 0; j < 8; ++j) {
            __half2 h = __floats2half2_rn(s[(2*j)*257 + tid], s[(2*j+1)*257 + tid]);
            r[j] = *(unsigned*)&h;
        }
        __half* dp = g_tfeat + (((y & ~1) << 11) | ((y & 1) << 5))
                             + (((x & ~1) << 5)  | ((x & 1) << 4));
        ((uint4*)dp)[0] = make_uint4(r[0], r[1], r[2], r[3]);
        ((uint4*)dp)[1] = make_uint4(r[4], r[5], r[6], r[7]);
    }

    // per-pixel hafm direction params (shared by all 5 residual lines)
    {
        const float PI = 3.14159265358979323846f;
        float md0 = md[idx], md1 = md[NPIX+idx], md2 = md[2*NPIX+idx];
        float md_un = (md0 - 0.5f) * (2.0f * PI);
        float cs  = cosf(md_un);
        float ss  = sinf(md_un);
        float yst = tanf(md1 * (PI * 0.5f));
        float yed = tanf(-md2 * (PI * 0.5f));
        g_lparam[idx] = make_float4(cs - ss*yst, ss + cs*yst,
                                    cs - ss*yed, ss + cs*yed);
    }

    float a = jloc[idx];
    float m = -1e30f;
    #pragma unroll
    for (int dy = -1; dy <= 1; ++dy) {
        int yy = y + dy;
        if (yy < 0 || yy >= HH) continue;
        #pragma unroll
        for (int dx = -1; dx <= 1; ++dx) {
            int xx = x + dx;
            if (xx < 0 || xx >= WW) continue;
            m = fmaxf(m, jloc[yy*WW + xx]);
        }
    }
    float v = (a == m) ? a : 0.0f;
    if (v > 0.0f) {
        int p = atomicAdd(&g_cnt[0], 1);
        g_cand_v[p] = v;
        g_cand_i[p] = idx;
    } else {
        int p = atomicAdd(&g_cnt[1], 1);
        g_zero_i[p] = idx;
    }
}

// Merged kernel: first TOPK_BLOCKS do rank-by-count top-k; the rest do LOI.
__global__ void __launch_bounds__(256, 6) k_main(
    float* __restrict__ out,
    const float* __restrict__ dis, const float* __restrict__ res,
    const float* __restrict__ joff, const int* __restrict__ topk)
{
    int lane = threadIdx.x & 31;

    if (blockIdx.x < TOPK_BLOCKS) {
        // ---- top-k: warp-per-candidate, stable (v desc, idx asc) ----
        int K = topk[0];
        int M = g_cnt[0];
        int Z = g_cnt[1];
        float* junc = out + (size_t)LOI_ELEMS;
        float* sc   = junc + 2*(size_t)K;
        int i = (blockIdx.x * blockDim.x + threadIdx.x) >> 5;

        if (i < M) {
            float v = g_cand_v[i];
            int  id = g_cand_i[i];
            int rank = 0;
            for (int j = lane; j < M; j += 32) {
                float vj = g_cand_v[j];
                int   ij = g_cand_i[j];
                rank += (int)((vj > v) | ((vj == v) & (ij < id)));
            }
            #pragma unroll
            for (int o = 16; o; o >>= 1) rank += __shfl_xor_sync(0xffffffffu, rank, o);
            if (lane == 0 && rank < K) {
                __stcs(&sc[rank], v);
                __stcs(&junc[2*rank+0], (float)(id & (WW-1)) + joff[id]        + 0.5f);
                __stcs(&junc[2*rank+1], (float)(id >> 7)     + joff[NPIX + id] + 0.5f);
            }
        }
        if (M < K && i < Z) {
            int zid = g_zero_i[i];
            int zr = 0;
            for (int j = lane; j < Z; j += 32)
                zr += (int)(g_zero_i[j] < zid);
            #pragma unroll
            for (int o = 16; o; o >>= 1) zr += __shfl_xor_sync(0xffffffffu, zr, o);
            int rk = M + zr;
            if (lane == 0 && rk < K) {
                __stcs(&sc[rk], 0.0f);
                __stcs(&junc[2*rk+0], (float)(zid & (WW-1)) + joff[zid]        + 0.5f);
                __stcs(&junc[2*rk+1], (float)(zid >> 7)     + joff[NPIX + zid] + 0.5f);
            }
        }

        // ---- deferred counter reset (replaces a reset kernel) ----
        __syncthreads();
        if (threadIdx.x == 0) {
            __threadfence();
            int d = atomicAdd(&g_done, 1);
            if (d == TOPK_BLOCKS - 1) {
                g_cnt[0] = 0;
                g_cnt[1] = 0;
                g_done   = 0;
                __threadfence();
            }
        }
        return;
    }

    // ---- LOI: one warp per line; params from precomputed per-pixel table ----
    int line = ((blockIdx.x - TOPK_BLOCKS) * blockDim.x + threadIdx.x) >> 5;
    int pix = line & (NPIX-1);
    int r   = line >> 14;               // residual index 0..4
    int x = pix & (WW-1), y = pix >> 7;

    float4 A = g_lparam[pix];           // warp-broadcast LDG.128
    float dist = fminf(fmaxf(dis[pix] + res[pix]*(float)(r-2), 0.0f), 1.0f) * SCALE;
    float fx = (float)x, fy = (float)y;
    float4 L;
    L.x = fminf(fmaxf(A.x*dist + fx, 0.0f), (float)(WW-1));
    L.y = fminf(fmaxf(A.y*dist + fy, 0.0f), (float)(HH-1));
    L.z = fminf(fmaxf(A.z*dist + fx, 0.0f), (float)(WW-1));
    L.w = fminf(fmaxf(A.w*dist + fy, 0.0f), (float)(HH-1));

    int c2 = lane >> 4;          // channel group: 0 or 1 (8 channels each)
    int tg = lane & 15;          // t-pair group: t = 2*tg + k

    const __half* fbase = g_tfeat + (c2 << 3);   // channel-half folded into base

    float2 acc[2][4];

    #pragma unroll
    for (int k = 0; k < 2; ++k) {
        float tf = (float)(2*tg + k) * (1.0f / 31.0f);
        float px = L.x*tf + L.z*(1.0f - tf) - 0.5f;
        float py = L.y*tf + L.w*(1.0f - tf) - 0.5f;

        float px0 = fminf(fmaxf(floorf(px), 0.0f), (float)(WW-1));
        float py0 = fminf(fmaxf(floorf(py), 0.0f), (float)(HH-1));
        float px1 = fminf(px0 + 1.0f, (float)(WW-1));
        float py1 = fminf(py0 + 1.0f, (float)(HH-1));
        float wx0 = px1 - px, wx1 = px - px0;
        float wy0 = py1 - py, wy1 = py - py0;
        __half2 h00 = __float2half2_rn(wy0*wx0);
        __half2 h10 = __float2half2_rn(wy1*wx0);
        __half2 h01 = __float2half2_rn(wy0*wx1);
        __half2 h11 = __float2half2_rn(wy1*wx1);
        int ix0 = (int)px0, iy0 = (int)py0, ix1 = (int)px1, iy1 = (int)py1;

        // separable quad addressing (half units)
        int X0 = ((ix0 & ~1) << 5) | ((ix0 & 1) << 4);
        int X1 = ((ix1 & ~1) << 5) | ((ix1 & 1) << 4);
        int Y0 = ((iy0 & ~1) << 11) | ((iy0 & 1) << 5);
        int Y1 = ((iy1 & ~1) << 11) | ((iy1 & 1) << 5);

        uint4 q00 = *(const uint4*)(fbase + (Y0 + X0));
        uint4 q10 = *(const uint4*)(fbase + (Y1 + X0));
        uint4 q01 = *(const uint4*)(fbase + (Y0 + X1));
        uint4 q11 = *(const uint4*)(fbase + (Y1 + X1));

        const __half2* a00 = (const __half2*)&q00;
        const __half2* a10 = (const __half2*)&q10;
        const __half2* a01 = (const __half2*)&q01;
        const __half2* a11 = (const __half2*)&q11;

        #pragma unroll
        for (int p = 0; p < 4; ++p) {
            __half2 s = __hmul2(a00[p], h00);
            s = __hfma2(a10[p], h10, s);
            s = __hfma2(a01[p], h01, s);
            s = __hfma2(a11[p], h11, s);
            acc[k][p] = __half22float2(s);
        }
    }

    // streaming stores: out is write-only, keep it out of L2
    float* row = out + (size_t)line * (CC*NPTS) + c2*(8*NPTS) + 2*tg;
    #pragma unroll
    for (int p = 0; p < 4; ++p) {
        __stcs((float2*)(row + (2*p  )*NPTS), make_float2(acc[0][p].x, acc[1][p].x));
        __stcs((float2*)(row + (2*p+1)*NPTS), make_float2(acc[0][p].y, acc[1][p].y));
    }
}

extern "C" void kernel_launch(void* const* d_in, const int* in_sizes, int n_in,
                              void* d_out, int out_size)
{
    const float* md   = (const float*)d_in[0];
    const float* dis  = (const float*)d_in[1];
    const float* res  = (const float*)d_in[2];
    const float* feat = (const float*)d_in[3];
    const float* jloc = (const float*)d_in[4];
    const float* joff = (const float*)d_in[5];
    const int*   topk = (const int*)d_in[6];
    float* out = (float*)d_out;

    k_prep<<<NPIX/256, 256>>>(feat, jloc, md);
    k_main<<<TOPK_BLOCKS + LOI_BLOCKS, 256>>>(out, dis, res, joff, topk);
}

// round 17
// speedup vs baseline: 1.0172x; 1.0172x over previous
#include <cuda_runtime.h>
#include <cuda_fp16.h>

#define HH 128
#define WW 128
#define CC 16
#define NPIX (HH*WW)
#define NRES 5
#define NLINES (NRES*NPIX)
#define NPTS 32
#define SCALE 5.0f
#define LOI_ELEMS (NLINES*CC*NPTS)
#define TOPK_BLOCKS (NPIX/8)        // 2048 blocks, 1 warp per candidate
#define LOI_BLOCKS  (NLINES/8)      // 10240 blocks, 1 warp per line

// scratch (no allocations allowed)
// g_tfeat layout: 2x2-pixel quads, 64 halfs (128B) per quad, separable:
//   half_index = Y(y) + X(x) + c,  Y(y)=(y&~1)<<11 | (y&1)<<5,  X(x)=(x&~1)<<5 | (x&1)<<4
__device__ __half g_tfeat[NPIX*CC];      // 0.5 MB
__device__ float4 g_lparam[NPIX];        // 256 KB, per-pixel (ax_st,ay_st,ax_ed,ay_ed)
__device__ float  g_cand_v[NPIX];
__device__ int    g_cand_i[NPIX];
__device__ int    g_zero_i[NPIX];
__device__ int    g_cnt[2];              // zero-init; self-resetting (see k_main)
__device__ int    g_done;                // zero-init; self-resetting

// features->fp16 quad-tiled, per-pixel hafm direction params, NMS + compaction
__global__ void __launch_bounds__(256) k_prep(
    const float* __restrict__ feat, const float* __restrict__ jloc,
    const float* __restrict__ md)
{
    __shared__ float s[CC*257];
    int tid = threadIdx.x;
    int idx = blockIdx.x * 256 + tid;
    int x = idx & (WW-1), y = idx >> 7;

    #pragma unroll
    for (int c = 0; c < CC; ++c)
        s[c*257 + tid] = feat[c*NPIX + idx];
    __syncthreads();
    {
        unsigned r[8];
        #pragma unroll
        for (int j = 0; j < 8; ++j) {
            __half2 h = __floats2half2_rn(s[(2*j)*257 + tid], s[(2*j+1)*257 + tid]);
            r[j] = *(unsigned*)&h;
        }
        __half* dp = g_tfeat + (((y & ~1) << 11) | ((y & 1) << 5))
                             + (((x & ~1) << 5)  | ((x & 1) << 4));
        ((uint4*)dp)[0] = make_uint4(r[0], r[1], r[2], r[3]);
        ((uint4*)dp)[1] = make_uint4(r[4], r[5], r[6], r[7]);
    }

    // per-pixel hafm direction params (shared by all 5 residual lines)
    {
        const float PI = 3.14159265358979323846f;
        float md0 = md[idx], md1 = md[NPIX+idx], md2 = md[2*NPIX+idx];
        float md_un = (md0 - 0.5f) * (2.0f * PI);
        float cs  = cosf(md_un);
        float ss  = sinf(md_un);
        float yst = tanf(md1 * (PI * 0.5f));
        float yed = tanf(-md2 * (PI * 0.5f));
        g_lparam[idx] = make_float4(cs - ss*yst, ss + cs*yst,
                                    cs - ss*yed, ss + cs*yed);
    }

    float a = jloc[idx];
    float m = -1e30f;
    #pragma unroll
    for (int dy = -1; dy <= 1; ++dy) {
        int yy = y + dy;
        if (yy < 0 || yy >= HH) continue;
        #pragma unroll
        for (int dx = -1; dx <= 1; ++dx) {
            int xx = x + dx;
            if (xx < 0 || xx >= WW) continue;
            m = fmaxf(m, jloc[yy*WW + xx]);
        }
    }
    float v = (a == m) ? a : 0.0f;
    if (v > 0.0f) {
        int p = atomicAdd(&g_cnt[0], 1);
        g_cand_v[p] = v;
        g_cand_i[p] = idx;
    } else {
        int p = atomicAdd(&g_cnt[1], 1);
        g_zero_i[p] = idx;
    }
}

// Merged kernel: first TOPK_BLOCKS do rank-by-count top-k; the rest do LOI.
__global__ void __launch_bounds__(256, 7) k_main(
    float* __restrict__ out,
    const float* __restrict__ dis, const float* __restrict__ res,
    const float* __restrict__ joff, const int* __restrict__ topk)
{
    int lane = threadIdx.x & 31;

    if (blockIdx.x < TOPK_BLOCKS) {
        // ---- top-k: warp-per-candidate, stable (v desc, idx asc) ----
        int K = topk[0];
        int M = g_cnt[0];
        int Z = g_cnt[1];
        float* junc = out + (size_t)LOI_ELEMS;
        float* sc   = junc + 2*(size_t)K;
        int i = (blockIdx.x * blockDim.x + threadIdx.x) >> 5;

        if (i < M) {
            float v = g_cand_v[i];
            int  id = g_cand_i[i];
            int rank = 0;
            for (int j = lane; j < M; j += 32) {
                float vj = g_cand_v[j];
                int   ij = g_cand_i[j];
                rank += (int)((vj > v) | ((vj == v) & (ij < id)));
            }
            #pragma unroll
            for (int o = 16; o; o >>= 1) rank += __shfl_xor_sync(0xffffffffu, rank, o);
            if (lane == 0 && rank < K) {
                __stcs(&sc[rank], v);
                __stcs(&junc[2*rank+0], (float)(id & (WW-1)) + joff[id]        + 0.5f);
                __stcs(&junc[2*rank+1], (float)(id >> 7)     + joff[NPIX + id] + 0.5f);
            }
        }
        if (M < K && i < Z) {
            int zid = g_zero_i[i];
            int zr = 0;
            for (int j = lane; j < Z; j += 32)
                zr += (int)(g_zero_i[j] < zid);
            #pragma unroll
            for (int o = 16; o; o >>= 1) zr += __shfl_xor_sync(0xffffffffu, zr, o);
            int rk = M + zr;
            if (lane == 0 && rk < K) {
                __stcs(&sc[rk], 0.0f);
                __stcs(&junc[2*rk+0], (float)(zid & (WW-1)) + joff[zid]        + 0.5f);
                __stcs(&junc[2*rk+1], (float)(zid >> 7)     + joff[NPIX + zid] + 0.5f);
            }
        }

        // ---- deferred counter reset (replaces a reset kernel) ----
        __syncthreads();
        if (threadIdx.x == 0) {
            __threadfence();
            int d = atomicAdd(&g_done, 1);
            if (d == TOPK_BLOCKS - 1) {
                g_cnt[0] = 0;
                g_cnt[1] = 0;
                g_done   = 0;
                __threadfence();
            }
        }
        return;
    }

    // ---- LOI: one warp per line; params from precomputed per-pixel table ----
    int line = ((blockIdx.x - TOPK_BLOCKS) * blockDim.x + threadIdx.x) >> 5;
    int pix = line & (NPIX-1);
    int r   = line >> 14;               // residual index 0..4
    int x = pix & (WW-1), y = pix >> 7;

    float4 A = g_lparam[pix];           // warp-broadcast LDG.128
    float dist = fminf(fmaxf(dis[pix] + res[pix]*(float)(r-2), 0.0f), 1.0f) * SCALE;
    float fx = (float)x, fy = (float)y;
    float4 L;
    L.x = fminf(fmaxf(A.x*dist + fx, 0.0f), (float)(WW-1));
    L.y = fminf(fmaxf(A.y*dist + fy, 0.0f), (float)(HH-1));
    L.z = fminf(fmaxf(A.z*dist + fx, 0.0f), (float)(WW-1));
    L.w = fminf(fmaxf(A.w*dist + fy, 0.0f), (float)(HH-1));

    int c2 = lane >> 4;          // channel group: 0 or 1 (8 channels each)
    int tg = lane & 15;          // t-pair group: t = 2*tg + k

    const __half* fbase = g_tfeat + (c2 << 3);   // channel-half folded into base

    float2 acc[2][4];

    #pragma unroll
    for (int k = 0; k < 2; ++k) {
        float tf = (float)(2*tg + k) * (1.0f / 31.0f);
        float px = L.x*tf + L.z*(1.0f - tf) - 0.5f;
        float py = L.y*tf + L.w*(1.0f - tf) - 0.5f;

        float px0 = fminf(fmaxf(floorf(px), 0.0f), (float)(WW-1));
        float py0 = fminf(fmaxf(floorf(py), 0.0f), (float)(HH-1));
        float px1 = fminf(px0 + 1.0f, (float)(WW-1));
        float py1 = fminf(py0 + 1.0f, (float)(HH-1));
        float wx0 = px1 - px, wx1 = px - px0;
        float wy0 = py1 - py, wy1 = py - py0;
        __half2 h00 = __float2half2_rn(wy0*wx0);
        __half2 h10 = __float2half2_rn(wy1*wx0);
        __half2 h01 = __float2half2_rn(wy0*wx1);
        __half2 h11 = __float2half2_rn(wy1*wx1);
        int ix0 = (int)px0, iy0 = (int)py0, ix1 = (int)px1, iy1 = (int)py1;

        // separable quad addressing (half units)
        int X0 = ((ix0 & ~1) << 5) | ((ix0 & 1) << 4);
        int X1 = ((ix1 & ~1) << 5) | ((ix1 & 1) << 4);
        int Y0 = ((iy0 & ~1) << 11) | ((iy0 & 1) << 5);
        int Y1 = ((iy1 & ~1) << 11) | ((iy1 & 1) << 5);

        uint4 q00 = *(const uint4*)(fbase + (Y0 + X0));
        uint4 q10 = *(const uint4*)(fbase + (Y1 + X0));
        uint4 q01 = *(const uint4*)(fbase + (Y0 + X1));
        uint4 q11 = *(const uint4*)(fbase + (Y1 + X1));

        const __half2* a00 = (const __half2*)&q00;
        const __half2* a10 = (const __half2*)&q10;
        const __half2* a01 = (const __half2*)&q01;
        const __half2* a11 = (const __half2*)&q11;

        #pragma unroll
        for (int p = 0; p < 4; ++p) {
            __half2 s = __hmul2(a00[p], h00);
            s = __hfma2(a10[p], h10, s);
            s = __hfma2(a01[p], h01, s);
            s = __hfma2(a11[p], h11, s);
            acc[k][p] = __half22float2(s);
        }
    }

    // streaming stores: out is write-only, keep it out of L2
    float* row = out + (size_t)line * (CC*NPTS) + c2*(8*NPTS) + 2*tg;
    #pragma unroll
    for (int p = 0; p < 4; ++p) {
        __stcs((float2*)(row + (2*p  )*NPTS), make_float2(acc[0][p].x, acc[1][p].x));
        __stcs((float2*)(row + (2*p+1)*NPTS), make_float2(acc[0][p].y, acc[1][p].y));
    }
}

extern "C" void kernel_launch(void* const* d_in, const int* in_sizes, int n_in,
                              void* d_out, int out_size)
{
    const float* md   = (const float*)d_in[0];
    const float* dis  = (const float*)d_in[1];
    const float* res  = (const float*)d_in[2];
    const float* feat = (const float*)d_in[3];
    const float* jloc = (const float*)d_in[4];
    const float* joff = (const float*)d_in[5];
    const int*   topk = (const int*)d_in[6];
    float* out = (float*)d_out;

    k_prep<<<NPIX/256, 256>>>(feat, jloc, md);
    k_main<<<TOPK_BLOCKS + LOI_BLOCKS, 256>>>(out, dis, res, joff, topk);
}